// round 14
// baseline (speedup 1.0000x reference)
#include <cuda_runtime.h>

#define GRID_BLOCKS 4096
#define BLOCK_THREADS 128

__device__ float g_sum = 0.0f;
__device__ unsigned int g_done_count = 0;

__global__ __launch_bounds__(BLOCK_THREADS, 16)
void mtnll_fused_kernel(const float* __restrict__ in0,
                        const float* __restrict__ in1,
                        const float* __restrict__ in2,
                        const float* __restrict__ cmap,
                        const int* __restrict__ t0,
                        const int* __restrict__ t1,
                        const int* __restrict__ t2,
                        float* __restrict__ out,
                        int n)
{
    float acc = 0.0f;

    // Simple scalar grid-stride, 7 independent load streams, L2-only loads.
    const int stride = gridDim.x * blockDim.x;
    for (int i = blockIdx.x * blockDim.x + threadIdx.x; i < n; i += stride) {
        const int   a = __ldcg(&t0[i]);
        const int   b = __ldcg(&t1[i]);
        const int   c = __ldcg(&t2[i]);
        const float w = __ldcg(&cmap[i]);
        const float p0 = __ldcg(&in0[3 * i + a]);
        const float p1 = __ldcg(&in1[3 * i + b]);
        const float p2 = __ldcg(&in2[3 * i + c]);
        const float s = fmaf(0.5f, p1, fmaf(0.25f, p2, p0));
        acc = fmaf(-w, s, acc);
    }

    // intra-block reduction
    #pragma unroll
    for (int o = 16; o > 0; o >>= 1)
        acc += __shfl_xor_sync(0xffffffffu, acc, o);

    __shared__ float smem[BLOCK_THREADS / 32];
    const int warp = threadIdx.x >> 5;
    const int lane = threadIdx.x & 31;
    if (lane == 0) smem[warp] = acc;
    __syncthreads();

    // thread 0: one atomic into a single device scalar, then elect last block
    if (threadIdx.x == 0) {
        float bsum = 0.0f;
        #pragma unroll
        for (int w = 0; w < BLOCK_THREADS / 32; w++) bsum += smem[w];
        atomicAdd(&g_sum, bsum);
        __threadfence();
        unsigned int prev = atomicAdd(&g_done_count, 1u);
        if (prev == gridDim.x - 1) {
            // all blocks' adds are visible (each fenced before bumping the count)
            float total = *((volatile float*)&g_sum);
            out[0] = total * (1.0f / (float)n);
            g_sum = 0.0f;        // reset for next graph replay
            g_done_count = 0;
        }
    }
}

extern "C" void kernel_launch(void* const* d_in, const int* in_sizes, int n_in,
                              void* d_out, int out_size) {
    const float* in0  = (const float*)d_in[0];
    const float* in1  = (const float*)d_in[1];
    const float* in2  = (const float*)d_in[2];
    const float* cmap = (const float*)d_in[3];
    const int* t0     = (const int*)d_in[4];
    const int* t1     = (const int*)d_in[5];
    const int* t2     = (const int*)d_in[6];
    float* out = (float*)d_out;

    const int n = in_sizes[3];

    mtnll_fused_kernel<<<GRID_BLOCKS, BLOCK_THREADS>>>(
        in0, in1, in2, cmap, t0, t1, t2, out, n);
}

// round 16
// speedup vs baseline: 1.1092x; 1.1092x over previous
#include <cuda_runtime.h>

#define GRID_BLOCKS 2048
#define BLOCK_THREADS 256

__device__ float g_sum = 0.0f;
__device__ unsigned int g_done_count = 0;

__global__ __launch_bounds__(BLOCK_THREADS, 8)
void mtnll_fused_kernel(const float* __restrict__ in0,
                        const float* __restrict__ in1,
                        const float* __restrict__ in2,
                        const float2* __restrict__ cmap2,
                        const int2* __restrict__ t0p,
                        const int2* __restrict__ t1p,
                        const int2* __restrict__ t2p,
                        float* __restrict__ out,
                        int n)                    // n = N (rows); N even
{
    float acc = 0.0f;

    // Each index p covers rows {2p, 2p+1}. Metadata paired as 64-bit loads,
    // logit gathers stay scalar (proven fastest pattern).
    const int np = n >> 1;
    const int stride = gridDim.x * blockDim.x;   // 524288 -> exactly 4 iters
    for (int p = blockIdx.x * blockDim.x + threadIdx.x; p < np; p += stride) {
        const int2   a2 = __ldg(&t0p[p]);
        const int2   b2 = __ldg(&t1p[p]);
        const int2   c2 = __ldg(&t2p[p]);
        const float2 w2 = __ldg(&cmap2[p]);

        const int r0 = 6 * p;       // base of row 2p in logits
        const int r1 = 6 * p + 3;   // base of row 2p+1

        const float p00 = __ldg(&in0[r0 + a2.x]);
        const float p01 = __ldg(&in1[r0 + b2.x]);
        const float p02 = __ldg(&in2[r0 + c2.x]);
        const float p10 = __ldg(&in0[r1 + a2.y]);
        const float p11 = __ldg(&in1[r1 + b2.y]);
        const float p12 = __ldg(&in2[r1 + c2.y]);

        const float s0 = fmaf(0.5f, p01, fmaf(0.25f, p02, p00));
        const float s1 = fmaf(0.5f, p11, fmaf(0.25f, p12, p10));
        acc = fmaf(-w2.x, s0, acc);
        acc = fmaf(-w2.y, s1, acc);
    }

    // intra-block reduction
    #pragma unroll
    for (int o = 16; o > 0; o >>= 1)
        acc += __shfl_xor_sync(0xffffffffu, acc, o);

    __shared__ float smem[BLOCK_THREADS / 32];
    const int warp = threadIdx.x >> 5;
    const int lane = threadIdx.x & 31;
    if (lane == 0) smem[warp] = acc;
    __syncthreads();

    // thread 0: one atomic into a single device scalar, then elect last block
    if (threadIdx.x == 0) {
        float bsum = 0.0f;
        #pragma unroll
        for (int w = 0; w < BLOCK_THREADS / 32; w++) bsum += smem[w];
        atomicAdd(&g_sum, bsum);
        __threadfence();
        unsigned int prev = atomicAdd(&g_done_count, 1u);
        if (prev == gridDim.x - 1) {
            // all blocks' adds are visible (each fenced before bumping the count)
            float total = *((volatile float*)&g_sum);
            out[0] = total * (1.0f / (float)n);
            g_sum = 0.0f;        // reset for next graph replay
            g_done_count = 0;
        }
    }
}

extern "C" void kernel_launch(void* const* d_in, const int* in_sizes, int n_in,
                              void* d_out, int out_size) {
    const float* in0    = (const float*)d_in[0];
    const float* in1    = (const float*)d_in[1];
    const float* in2    = (const float*)d_in[2];
    const float2* cmap2 = (const float2*)d_in[3];
    const int2* t0p     = (const int2*)d_in[4];
    const int2* t1p     = (const int2*)d_in[5];
    const int2* t2p     = (const int2*)d_in[6];
    float* out = (float*)d_out;

    const int n = in_sizes[3];   // N, even

    mtnll_fused_kernel<<<GRID_BLOCKS, BLOCK_THREADS>>>(
        in0, in1, in2, cmap2, t0p, t1p, t2p, out, n);
}